// round 1
// baseline (speedup 1.0000x reference)
#include <cuda_runtime.h>
#include <cstdint>

#define FULL_MASK 0xffffffffu

__global__ void ord_zero_kernel(float* out) {
    if (threadIdx.x == 0 && blockIdx.x == 0) *out = 0.0f;
}

__device__ __forceinline__ float softplus_f(float u) {
    // log(1 + exp(u)), numerically stable; 2 MUFU (EX2 + LG2) via fast intrinsics.
    return fmaxf(u, 0.0f) + __logf(1.0f + __expf(-fabsf(u)));
}

__global__ __launch_bounds__(256, 8) void ord_loss_kernel(
    const float* __restrict__ logits,
    const long long* __restrict__ targets,
    float* __restrict__ out,
    int B)
{
    const int lane  = threadIdx.x & 31;
    const int wib   = threadIdx.x >> 5;
    const int gwarp = blockIdx.x * (blockDim.x >> 5) + wib;
    const int nwarp = gridDim.x * (blockDim.x >> 5);

    float acc = 0.0f;

    for (int row = gwarp; row < B; row += nwarp) {
        const float4* rp = reinterpret_cast<const float4*>(logits + (size_t)row * 256);
        // Issue both loads up front for MLP=2
        float4 v0 = rp[lane];
        float4 v1 = rp[lane + 32];
        const int t = (int)targets[row];

        float carry = 0.0f;
        #pragma unroll
        for (int j = 0; j < 2; ++j) {
            float4 v = (j == 0) ? v0 : v1;
            // local 4-element inclusive prefix
            float p0 = v.x;
            float p1 = p0 + v.y;
            float p2 = p1 + v.z;
            float p3 = p2 + v.w;
            // warp inclusive scan of lane sums
            float s = p3;
            #pragma unroll
            for (int o = 1; o < 32; o <<= 1) {
                float n = __shfl_up_sync(FULL_MASK, s, o);
                if (lane >= o) s += n;
            }
            float base = carry + (s - p3);       // exclusive prefix + carry
            carry += __shfl_sync(FULL_MASK, s, 31);

            float c0 = base + p0;
            float c1 = base + p1;
            float c2 = base + p2;
            float c3 = base + p3;

            int k = j * 128 + lane * 4;
            // per_elem = softplus(-sign*cum); sign=-1 when k<t -> u = cum, else u = -cum
            float u0 = (k + 0 < t) ? c0 : -c0;
            float u1 = (k + 1 < t) ? c1 : -c1;
            float u2 = (k + 2 < t) ? c2 : -c2;
            float u3 = (k + 3 < t) ? c3 : -c3;

            acc += softplus_f(u0);
            acc += softplus_f(u1);
            acc += softplus_f(u2);
            if (k + 3 < 255) acc += softplus_f(u3);   // drop k == 255 only
        }
    }

    // warp reduce
    #pragma unroll
    for (int o = 16; o; o >>= 1) acc += __shfl_xor_sync(FULL_MASK, acc, o);

    __shared__ float ws[8];
    if (lane == 0) ws[wib] = acc;
    __syncthreads();
    if (threadIdx.x == 0) {
        float s = 0.0f;
        #pragma unroll
        for (int i = 0; i < 8; ++i) s += ws[i];
        atomicAdd(out, s * (1.0f / (float)B));
    }
}

extern "C" void kernel_launch(void* const* d_in, const int* in_sizes, int n_in,
                              void* d_out, int out_size)
{
    const float*     logits  = (const float*)d_in[0];
    const long long* targets = (const long long*)d_in[1];
    float*           out     = (float*)d_out;

    const int B = in_sizes[1];          // number of rows (targets count)

    ord_zero_kernel<<<1, 32>>>(out);

    const int threads = 256;
    const int blocks  = 2048;           // ~16K warps, grid-stride over rows
    ord_loss_kernel<<<blocks, threads>>>(logits, targets, out, B);
}

// round 5
// speedup vs baseline: 1.0401x; 1.0401x over previous
#include <cuda_runtime.h>

#define FULL_MASK 0xffffffffu

__global__ void ord_zero_kernel(float* out) {
    if (threadIdx.x == 0 && blockIdx.x == 0) *out = 0.0f;
}

__device__ __forceinline__ float ex2f(float x) {
    float y; asm("ex2.approx.ftz.f32 %0, %1;" : "=f"(y) : "f"(x)); return y;
}
__device__ __forceinline__ float lg2f(float x) {
    float y; asm("lg2.approx.ftz.f32 %0, %1;" : "=f"(y) : "f"(x)); return y;
}

__global__ __launch_bounds__(256, 8) void ord_loss_kernel(
    const float* __restrict__ logits,
    const long long* __restrict__ targets,
    float* __restrict__ out,
    int B)
{
    const int lane  = threadIdx.x & 31;
    const int wib   = threadIdx.x >> 5;
    const int gwarp = blockIdx.x * (blockDim.x >> 5) + wib;
    const int nwarp = gridDim.x * (blockDim.x >> 5);

    // Three accumulators:
    //   acc_a  = sum |c|          (abs part of relu)
    //   acc_s  = sum (k<t ? c : -c)   (signed part of relu; u = +c when k<t)
    //   acc_l2 = sum log2(prod_row)   (softplus tail, via product trick)
    float acc_a = 0.0f, acc_s = 0.0f, acc_l2 = 0.0f;

    const float NEG_LOG2E = -1.442695041f;

    int row = gwarp;
    float4 v0, v1; int t = 0;
    if (row < B) {
        const float4* rp = reinterpret_cast<const float4*>(logits + (size_t)row * 256);
        v0 = rp[lane];
        v1 = rp[lane + 32];
        t  = *(const int*)(targets + row);   // little-endian low word, value < 256
    }

    while (row < B) {
        const int nrow = row + nwarp;
        float4 nv0, nv1; int nt = 0;
        if (nrow < B) {
            const float4* rp = reinterpret_cast<const float4*>(logits + (size_t)nrow * 256);
            nv0 = rp[lane];
            nv1 = rp[lane + 32];
            nt  = *(const int*)(targets + nrow);
        }

        float carry = 0.0f;
        float prod  = 1.0f;      // product of (1 + e^{-|c_k|}) over this lane's elements of the row

        #pragma unroll
        for (int j = 0; j < 2; ++j) {
            float4 v = (j == 0) ? v0 : v1;
            // local 4-element inclusive prefix
            float p0 = v.x;
            float p1 = p0 + v.y;
            float p2 = p1 + v.z;
            float p3 = p2 + v.w;
            // warp inclusive scan of lane totals
            float s = p3;
            #pragma unroll
            for (int o = 1; o < 32; o <<= 1) {
                float n = __shfl_up_sync(FULL_MASK, s, o);
                if (lane >= o) s += n;
            }
            float base = carry + (s - p3);
            carry += __shfl_sync(FULL_MASK, s, 31);

            float c0 = base + p0;
            float c1 = base + p1;
            float c2 = base + p2;
            float c3 = base + p3;

            const int k0 = j * 128 + lane * 4;

            {
                float a = fabsf(c0);
                float e = ex2f(a * NEG_LOG2E);
                prod  = fmaf(prod, e, prod);        // prod *= (1 + e)
                acc_a += a;
                acc_s += (k0 < t) ? c0 : -c0;
            }
            {
                float a = fabsf(c1);
                float e = ex2f(a * NEG_LOG2E);
                prod  = fmaf(prod, e, prod);
                acc_a += a;
                acc_s += (k0 + 1 < t) ? c1 : -c1;
            }
            {
                float a = fabsf(c2);
                float e = ex2f(a * NEG_LOG2E);
                prod  = fmaf(prod, e, prod);
                acc_a += a;
                acc_s += (k0 + 2 < t) ? c2 : -c2;
            }
            if (k0 + 3 < 255) {                      // excludes only k == 255
                float a = fabsf(c3);
                float e = ex2f(a * NEG_LOG2E);
                prod  = fmaf(prod, e, prod);
                acc_a += a;
                acc_s += (k0 + 3 < t) ? c3 : -c3;
            }
        }

        acc_l2 += lg2f(prod);    // one LG2 per row instead of one per element

        v0 = nv0; v1 = nv1; t = nt;
        row = nrow;
    }

    // combine: sum softplus = 0.5*(acc_a + acc_s) + ln2 * acc_l2
    float r = 0.5f * (acc_a + acc_s) + 0.69314718056f * acc_l2;

    #pragma unroll
    for (int o = 16; o; o >>= 1) r += __shfl_xor_sync(FULL_MASK, r, o);

    __shared__ float ws[8];
    if (lane == 0) ws[wib] = r;
    __syncthreads();
    if (threadIdx.x == 0) {
        float ssum = 0.0f;
        #pragma unroll
        for (int i = 0; i < 8; ++i) ssum += ws[i];
        atomicAdd(out, ssum * (1.0f / (float)B));
    }
}

extern "C" void kernel_launch(void* const* d_in, const int* in_sizes, int n_in,
                              void* d_out, int out_size)
{
    const float*     logits  = (const float*)d_in[0];
    const long long* targets = (const long long*)d_in[1];
    float*           out     = (float*)d_out;

    const int B = in_sizes[1];

    ord_zero_kernel<<<1, 32>>>(out);
    ord_loss_kernel<<<2048, 256>>>(logits, targets, out, B);
}

// round 7
// speedup vs baseline: 1.0722x; 1.0309x over previous
#include <cuda_runtime.h>

#define FULL_MASK 0xffffffffu

__global__ void ord_zero_kernel(float* out) {
    if (threadIdx.x == 0 && blockIdx.x == 0) *out = 0.0f;
}

__device__ __forceinline__ float ex2f(float x) {
    float y; asm("ex2.approx.ftz.f32 %0, %1;" : "=f"(y) : "f"(x)); return y;
}
__device__ __forceinline__ float lg2f(float x) {
    float y; asm("lg2.approx.ftz.f32 %0, %1;" : "=f"(y) : "f"(x)); return y;
}

__global__ __launch_bounds__(256, 8) void ord_loss_kernel(
    const float* __restrict__ logits,
    const long long* __restrict__ targets,
    float* __restrict__ out,
    int B)
{
    const int lane  = threadIdx.x & 31;
    const int wib   = threadIdx.x >> 5;
    const int gwarp = blockIdx.x * (blockDim.x >> 5) + wib;
    const int nwarp = gridDim.x * (blockDim.x >> 5);

    const bool last_lane = (lane == 31);
    const float NEG_LOG2E = -1.4426950408889634f;

    // acc_r  = sum max(u,0)   (relu part of softplus)
    // acc_l2 = sum log2(prod) (tail part; prod = prod of (1+e^{-|c|}) per row-lane)
    float acc_r = 0.0f, acc_l2 = 0.0f;

    const float4* base4 = reinterpret_cast<const float4*>(logits);

    int row = gwarp;
    float4 a0, a1; int t = 0;
    if (row < B) {
        const float4* rp = base4 + (size_t)row * 64;
        a0 = rp[2 * lane];
        a1 = rp[2 * lane + 1];
        t  = *(const int*)(targets + row);     // low word of int64, value in [0,255]
    }

    while (row < B) {
        const int nrow = row + nwarp;
        float4 b0, b1; int nt = 0;
        if (nrow < B) {
            const float4* rp = base4 + (size_t)nrow * 64;
            b0 = rp[2 * lane];
            b1 = rp[2 * lane + 1];
            nt = *(const int*)(targets + nrow);
        }

        // lane owns contiguous elements k = 8*lane + i, i in [0,8)
        float p0 = a0.x;
        float p1 = p0 + a0.y;
        float p2 = p1 + a0.z;
        float p3 = p2 + a0.w;
        float p4 = p3 + a1.x;
        float p5 = p4 + a1.y;
        float p6 = p5 + a1.z;
        float p7 = p6 + a1.w;

        // single warp inclusive scan of lane totals
        float s = p7;
        #pragma unroll
        for (int o = 1; o < 32; o <<= 1) {
            float n = __shfl_up_sync(FULL_MASK, s, o);
            if (lane >= o) s += n;
        }
        const float cbase = s - p7;            // exclusive prefix for this lane
        const int   kt    = t - 8 * lane;      // i < kt  <=>  k < t

        float prod = 1.0f;
        float pl[8] = {p0, p1, p2, p3, p4, p5, p6, p7};

        #pragma unroll
        for (int i = 0; i < 8; ++i) {
            float c = cbase + pl[i];
            float u = (i < kt) ? c : -c;
            float e = ex2f(fabsf(c) * NEG_LOG2E);   // e^{-|c|}
            if (i == 7) {                            // exclude k == 255 (lane 31 only)
                u = last_lane ? -1.0f : u;
                e = last_lane ?  0.0f : e;
            }
            acc_r += fmaxf(u, 0.0f);
            prod   = fmaf(prod, e, prod);            // prod *= (1 + e)
        }

        acc_l2 += lg2f(prod);

        a0 = b0; a1 = b1; t = nt;
        row = nrow;
    }

    float r = fmaf(0.69314718055994531f, acc_l2, acc_r);

    #pragma unroll
    for (int o = 16; o; o >>= 1) r += __shfl_xor_sync(FULL_MASK, r, o);

    __shared__ float ws[8];
    if (lane == 0) ws[wib] = r;
    __syncthreads();
    if (threadIdx.x == 0) {
        float ssum = 0.0f;
        #pragma unroll
        for (int i = 0; i < 8; ++i) ssum += ws[i];
        atomicAdd(out, ssum * (1.0f / (float)B));
    }
}

extern "C" void kernel_launch(void* const* d_in, const int* in_sizes, int n_in,
                              void* d_out, int out_size)
{
    const float*     logits  = (const float*)d_in[0];
    const long long* targets = (const long long*)d_in[1];
    float*           out     = (float*)d_out;

    const int B = in_sizes[1];

    ord_zero_kernel<<<1, 32>>>(out);
    ord_loss_kernel<<<2048, 256>>>(logits, targets, out, B);
}

// round 10
// speedup vs baseline: 1.1152x; 1.0401x over previous
#include <cuda_runtime.h>

#define FULL_MASK 0xffffffffu

__global__ void ord_zero_kernel(float* out) {
    if (threadIdx.x == 0 && blockIdx.x == 0) *out = 0.0f;
}

__device__ __forceinline__ float ex2f(float x) {
    float y; asm("ex2.approx.ftz.f32 %0, %1;" : "=f"(y) : "f"(x)); return y;
}
__device__ __forceinline__ float lg2f(float x) {
    float y; asm("lg2.approx.ftz.f32 %0, %1;" : "=f"(y) : "f"(x)); return y;
}

// One row per 16-lane segment; each warp iteration processes 2 rows.
// Each lane owns 16 contiguous elements (4 consecutive float4 loads).
__global__ __launch_bounds__(256, 5) void ord_loss_kernel(
    const float* __restrict__ logits,
    const long long* __restrict__ targets,
    float* __restrict__ out,
    int B)
{
    const int lane = threadIdx.x & 31;
    const int sl   = lane & 15;          // lane within segment
    const int seg  = lane >> 4;          // 0 or 1: which row of the pair
    const int wib  = threadIdx.x >> 5;
    const int gwarp = blockIdx.x * (blockDim.x >> 5) + wib;
    const int nwarp = gridDim.x * (blockDim.x >> 5);

    const bool tail_lane = (sl == 15);   // owns element k == 255
    const float NEG_LOG2E = -1.4426950408889634f;

    float acc_r = 0.0f, acc_l2 = 0.0f;

    const float4* base4 = reinterpret_cast<const float4*>(logits);
    const int npairs = (B + 1) >> 1;

    int pair = gwarp;
    float4 a0, a1, a2, a3; int t = 0;
    {
        int row = pair * 2 + seg;
        if (row < B) {
            const float4* rp = base4 + (size_t)row * 64 + sl * 4;
            a0 = rp[0]; a1 = rp[1]; a2 = rp[2]; a3 = rp[3];
            t  = *(const int*)(targets + row);
        }
    }

    while (pair < npairs) {
        const int npair = pair + nwarp;
        float4 b0, b1, b2, b3; int nt = 0;
        if (npair < npairs) {
            int nr = npair * 2 + seg;
            if (nr < B) {
                const float4* rp = base4 + (size_t)nr * 64 + sl * 4;
                b0 = rp[0]; b1 = rp[1]; b2 = rp[2]; b3 = rp[3];
                nt = *(const int*)(targets + nr);
            }
        }

        // 16-element local inclusive prefix (contiguous: k = 16*sl + i)
        float p[16];
        p[0]  = a0.x;         p[1]  = p[0]  + a0.y;
        p[2]  = p[1]  + a0.z; p[3]  = p[2]  + a0.w;
        p[4]  = p[3]  + a1.x; p[5]  = p[4]  + a1.y;
        p[6]  = p[5]  + a1.z; p[7]  = p[6]  + a1.w;
        p[8]  = p[7]  + a2.x; p[9]  = p[8]  + a2.y;
        p[10] = p[9]  + a2.z; p[11] = p[10] + a2.w;
        p[12] = p[11] + a3.x; p[13] = p[12] + a3.y;
        p[14] = p[13] + a3.z; p[15] = p[14] + a3.w;

        // segmented (16-lane) inclusive scan of lane totals
        float s = p[15];
        #pragma unroll
        for (int o = 1; o < 16; o <<= 1) {
            float n = __shfl_up_sync(FULL_MASK, s, o);
            if (sl >= o) s += n;
        }
        const float cbase = s - p[15];     // exclusive prefix within the row
        const int   kt    = t - 16 * sl;   // i < kt  <=>  k < t

        float rrel = 0.0f;
        float prod = 1.0f;

        #pragma unroll
        for (int i = 0; i < 16; ++i) {
            float c = cbase + p[i];
            float u = (i < kt) ? c : -c;
            float e = ex2f(fabsf(c) * NEG_LOG2E);   // e^{-|c|}
            if (i == 15) {                          // exclude k == 255
                u = tail_lane ? -1.0f : u;
                e = tail_lane ?  0.0f : e;
            }
            rrel += fmaxf(u, 0.0f);
            prod  = fmaf(prod, e, prod);            // prod *= (1 + e)
        }

        if (pair * 2 + seg < B) {
            acc_r  += rrel;
            acc_l2 += lg2f(prod);
        }

        a0 = b0; a1 = b1; a2 = b2; a3 = b3; t = nt;
        pair = npair;
    }

    float r = fmaf(0.69314718055994531f, acc_l2, acc_r);

    #pragma unroll
    for (int o = 16; o; o >>= 1) r += __shfl_xor_sync(FULL_MASK, r, o);

    __shared__ float ws[8];
    if (lane == 0) ws[wib] = r;
    __syncthreads();
    if (threadIdx.x == 0) {
        float ssum = 0.0f;
        #pragma unroll
        for (int i = 0; i < 8; ++i) ssum += ws[i];
        atomicAdd(out, ssum * (1.0f / (float)B));
    }
}

extern "C" void kernel_launch(void* const* d_in, const int* in_sizes, int n_in,
                              void* d_out, int out_size)
{
    const float*     logits  = (const float*)d_in[0];
    const long long* targets = (const long long*)d_in[1];
    float*           out     = (float*)d_out;

    const int B = in_sizes[1];

    ord_zero_kernel<<<1, 32>>>(out);
    ord_loss_kernel<<<2048, 256>>>(logits, targets, out, B);
}

// round 11
// speedup vs baseline: 1.1764x; 1.0549x over previous
#include <cuda_runtime.h>

#define FULL_MASK 0xffffffffu

__global__ void ord_zero_kernel(float* out) {
    if (threadIdx.x == 0 && blockIdx.x == 0) *out = 0.0f;
}

__device__ __forceinline__ float ex2f(float x) {
    float y; asm("ex2.approx.ftz.f32 %0, %1;" : "=f"(y) : "f"(x)); return y;
}
__device__ __forceinline__ float lg2f(float x) {
    float y; asm("lg2.approx.ftz.f32 %0, %1;" : "=f"(y) : "f"(x)); return y;
}

// Warp-per-row, 8 contiguous elements per lane (fully coalesced LDG.128 x2),
// depth-2 software pipeline (two row buffers in flight).
__global__ __launch_bounds__(256, 5) void ord_loss_kernel(
    const float* __restrict__ logits,
    const long long* __restrict__ targets,
    float* __restrict__ out,
    int Btot)
{
    const int lane  = threadIdx.x & 31;
    const int wib   = threadIdx.x >> 5;
    const int gwarp = blockIdx.x * (blockDim.x >> 5) + wib;
    const int nwarp = gridDim.x * (blockDim.x >> 5);

    const bool last_lane = (lane == 31);
    const float NEG_LOG2E = -1.4426950408889634f;

    float acc_r = 0.0f, acc_l2 = 0.0f;

    const float4* base4 = reinterpret_cast<const float4*>(logits);

    // Pipeline buffers: X holds row `row`, Y holds row `row + nwarp`.
    float4 x0, x1, y0, y1;
    int tx = 0, ty = 0;

    int row = gwarp;
    if (row < Btot) {
        const float4* rp = base4 + (size_t)row * 64;
        x0 = rp[2 * lane];
        x1 = rp[2 * lane + 1];
        tx = *(const int*)(targets + row);
    }
    if (row + nwarp < Btot) {
        const float4* rp = base4 + (size_t)(row + nwarp) * 64;
        y0 = rp[2 * lane];
        y1 = rp[2 * lane + 1];
        ty = *(const int*)(targets + (row + nwarp));
    }

    while (true) {
        // ---- process X (row), prefetch row+2nw into X ----
        if (row >= Btot) break;
        {
            float p0 = x0.x;
            float p1 = p0 + x0.y;
            float p2 = p1 + x0.z;
            float p3 = p2 + x0.w;
            float p4 = p3 + x1.x;
            float p5 = p4 + x1.y;
            float p6 = p5 + x1.z;
            float p7 = p6 + x1.w;
            const int kt = tx - 8 * lane;

            const int pf = row + 2 * nwarp;
            if (pf < Btot) {
                const float4* rp = base4 + (size_t)pf * 64;
                x0 = rp[2 * lane];
                x1 = rp[2 * lane + 1];
                tx = *(const int*)(targets + pf);
            }

            float s = p7;
            #pragma unroll
            for (int o = 1; o < 32; o <<= 1) {
                float n = __shfl_up_sync(FULL_MASK, s, o);
                if (lane >= o) s += n;
            }
            const float cbase = s - p7;

            float prod = 1.0f;
            float pl[8] = {p0, p1, p2, p3, p4, p5, p6, p7};
            #pragma unroll
            for (int i = 0; i < 8; ++i) {
                float c = cbase + pl[i];
                float u = (i < kt) ? c : -c;
                float e = ex2f(fabsf(c) * NEG_LOG2E);
                if (i == 7) {
                    u = last_lane ? -1.0f : u;
                    e = last_lane ?  0.0f : e;
                }
                acc_r += fmaxf(u, 0.0f);
                prod   = fmaf(prod, e, prod);
            }
            acc_l2 += lg2f(prod);
        }
        row += nwarp;

        // ---- process Y (row), prefetch row+2nw into Y ----
        if (row >= Btot) break;
        {
            float p0 = y0.x;
            float p1 = p0 + y0.y;
            float p2 = p1 + y0.z;
            float p3 = p2 + y0.w;
            float p4 = p3 + y1.x;
            float p5 = p4 + y1.y;
            float p6 = p5 + y1.z;
            float p7 = p6 + y1.w;
            const int kt = ty - 8 * lane;

            const int pf = row + 2 * nwarp;
            if (pf < Btot) {
                const float4* rp = base4 + (size_t)pf * 64;
                y0 = rp[2 * lane];
                y1 = rp[2 * lane + 1];
                ty = *(const int*)(targets + pf);
            }

            float s = p7;
            #pragma unroll
            for (int o = 1; o < 32; o <<= 1) {
                float n = __shfl_up_sync(FULL_MASK, s, o);
                if (lane >= o) s += n;
            }
            const float cbase = s - p7;

            float prod = 1.0f;
            float pl[8] = {p0, p1, p2, p3, p4, p5, p6, p7};
            #pragma unroll
            for (int i = 0; i < 8; ++i) {
                float c = cbase + pl[i];
                float u = (i < kt) ? c : -c;
                float e = ex2f(fabsf(c) * NEG_LOG2E);
                if (i == 7) {
                    u = last_lane ? -1.0f : u;
                    e = last_lane ?  0.0f : e;
                }
                acc_r += fmaxf(u, 0.0f);
                prod   = fmaf(prod, e, prod);
            }
            acc_l2 += lg2f(prod);
        }
        row += nwarp;
    }

    float r = fmaf(0.69314718055994531f, acc_l2, acc_r);

    #pragma unroll
    for (int o = 16; o; o >>= 1) r += __shfl_xor_sync(FULL_MASK, r, o);

    __shared__ float ws[8];
    if (lane == 0) ws[wib] = r;
    __syncthreads();
    if (threadIdx.x == 0) {
        float ssum = 0.0f;
        #pragma unroll
        for (int i = 0; i < 8; ++i) ssum += ws[i];
        atomicAdd(out, ssum * (1.0f / (float)Btot));
    }
}

extern "C" void kernel_launch(void* const* d_in, const int* in_sizes, int n_in,
                              void* d_out, int out_size)
{
    const float*     logits  = (const float*)d_in[0];
    const long long* targets = (const long long*)d_in[1];
    float*           out     = (float*)d_out;

    const int B = in_sizes[1];

    ord_zero_kernel<<<1, 32>>>(out);
    ord_loss_kernel<<<2048, 256>>>(logits, targets, out, B);
}